// round 10
// baseline (speedup 1.0000x reference)
#include <cuda_runtime.h>
#include <math.h>

// Problem constants
#define Bn   8
#define LQ   8192
#define LK   1024
#define NF   64

// Scratch for projected K (transposed, [b][e][k]) and V ([b][k][e])
__device__ __align__(16) float g_Kt[Bn * NF * LK];
__device__ __align__(16) float g_V [Bn * LK * NF];

// ---------------------------------------------------------------------------
// Kernel 1: project kv -> K^T (transposed) and V.
// grid = Bn * (LK/64) = 128 blocks, 256 threads.
// ---------------------------------------------------------------------------
__global__ __launch_bounds__(256) void kvproj_kernel(
    const float* __restrict__ kv,
    const float* __restrict__ Wk,
    const float* __restrict__ Wv)
{
    int b  = blockIdx.x >> 4;
    int kt = blockIdx.x & 15;
    int k0 = kt * 64;

    extern __shared__ float sm[];
    float* s_kv = sm;            // 64 x 64
    float* s_w  = sm + 4096;     // 64 x 64
    float* s_ko = sm + 8192;     // 64 x 65

    int tid = threadIdx.x;

    for (int i = tid; i < 4096; i += 256)
        s_kv[i] = kv[(b * LK + k0) * NF + i];
    for (int i = tid; i < 4096; i += 256)
        s_w[i] = Wv[i];
    __syncthreads();

    // V = kv @ Wv, written directly (coalesced over e)
    for (int i = tid; i < 4096; i += 256) {
        int k = i >> 6, e = i & 63;
        float acc = 0.f;
#pragma unroll
        for (int d = 0; d < 64; d++)
            acc += s_kv[k * 64 + d] * s_w[d * 64 + e];
        g_V[(b * LK + k0 + k) * NF + e] = acc;
    }
    __syncthreads();

    for (int i = tid; i < 4096; i += 256)
        s_w[i] = Wk[i];
    __syncthreads();

    // K = kv @ Wk into smem, then transposed coalesced store to g_Kt
    for (int i = tid; i < 4096; i += 256) {
        int k = i >> 6, e = i & 63;
        float acc = 0.f;
#pragma unroll
        for (int d = 0; d < 64; d++)
            acc += s_kv[k * 64 + d] * s_w[d * 64 + e];
        s_ko[k * 65 + e] = acc;
    }
    __syncthreads();

    for (int i = tid; i < 4096; i += 256) {
        int e = i >> 6, k = i & 63;
        g_Kt[(b * NF + e) * LK + k0 + k] = s_ko[k * 65 + e];
    }
}

// ---------------------------------------------------------------------------
// Kernel 2: fused Q-projection + flash attention.
// grid = Bn * (LQ/128) = 512 blocks, 256 threads (16 ty x 16 tx).
// Score stage : 8x8 micro-tile  -> 128 q x 128 k   per CTA iter.
// PV stage    : 8x4 micro-tile  -> 128 q x  64 dim per CTA.
// ---------------------------------------------------------------------------
#define QS_STRIDE 132
#define PS_STRIDE 132

__global__ __launch_bounds__(256, 1) void attn_kernel(
    const float* __restrict__ x,
    const float* __restrict__ Wq,
    float* __restrict__ out)
{
    int b  = blockIdx.x >> 6;
    int qt = blockIdx.x & 63;
    int q0 = qt * 128;

    extern __shared__ float sm[];
    float* Qs = sm;                      // 64*132 = 8448
    float* Ks = Qs + 64 * QS_STRIDE;     // 8192
    float* Vs = Ks + 64 * 128;           // 8192
    float* Ps = Vs + 128 * 64;           // 128*132 = 16896
    float* Wqs = Ps;                     // prologue alias
    float* Xs  = Ps + 4096;              // prologue alias

    int tid = threadIdx.x;
    int ty  = tid >> 4;      // 0..15 : query group (8 rows)
    int tx  = tid & 15;      // 0..15 : key group (8) / dim group (4)

    // ---- prologue: load Wq + x tile, compute Q^T into Qs ----
    for (int i = tid; i < 4096; i += 256) Wqs[i] = Wq[i];
    for (int i = tid; i < 8192; i += 256) Xs[i] = x[(b * LQ + q0) * NF + i];
    __syncthreads();

    for (int i = tid; i < 8192; i += 256) {
        int q = i >> 6, e = i & 63;
        float acc = 0.f;
#pragma unroll
        for (int d = 0; d < 64; d++)
            acc += Xs[q * 64 + d] * Wqs[d * 64 + e];
        Qs[e * QS_STRIDE + q] = acc;
    }
    __syncthreads();

    // ---- accumulators: 8 queries x 4 output dims per thread ----
    float O[8][4];
    float m[8], l[8];
#pragma unroll
    for (int qi = 0; qi < 8; qi++) {
        m[qi] = -3.0e38f;
        l[qi] = 0.f;
#pragma unroll
        for (int dj = 0; dj < 4; dj++) O[qi][dj] = 0.f;
    }

    // ---- main loop over 8 key tiles of 128 ----
    for (int kt = 0; kt < 8; kt++) {
        // load K^T tile [64 e][128 k] and V tile [128 k][64 e]
        for (int i = tid; i < 2048; i += 256) {
            int e = i >> 5, c = i & 31;
            *(float4*)(Ks + e * 128 + c * 4) =
                *(const float4*)(g_Kt + (b * NF + e) * LK + kt * 128 + c * 4);
        }
        for (int i = tid; i < 2048; i += 256) {
            int k = i >> 4, c = i & 15;
            *(float4*)(Vs + k * 64 + c * 4) =
                *(const float4*)(g_V + (b * LK + kt * 128 + k) * NF + c * 4);
        }
        __syncthreads();

        // ---- scores: S[8q][8k] ----
        float s[8][8];
#pragma unroll
        for (int qi = 0; qi < 8; qi++)
#pragma unroll
            for (int kj = 0; kj < 8; kj++) s[qi][kj] = 0.f;

#pragma unroll 8
        for (int d = 0; d < 64; d++) {
            float4 a0 = *(const float4*)(Qs + d * QS_STRIDE + ty * 8);
            float4 a1 = *(const float4*)(Qs + d * QS_STRIDE + ty * 8 + 4);
            float4 b0 = *(const float4*)(Ks + d * 128 + tx * 8);
            float4 b1 = *(const float4*)(Ks + d * 128 + tx * 8 + 4);
            float aq[8] = {a0.x, a0.y, a0.z, a0.w, a1.x, a1.y, a1.z, a1.w};
            float bk[8] = {b0.x, b0.y, b0.z, b0.w, b1.x, b1.y, b1.z, b1.w};
#pragma unroll
            for (int qi = 0; qi < 8; qi++)
#pragma unroll
                for (int kj = 0; kj < 8; kj++)
                    s[qi][kj] += aq[qi] * bk[kj];
        }

        // ---- online softmax (row reduction across 16 tx lanes) ----
#pragma unroll
        for (int qi = 0; qi < 8; qi++) {
            float tmax = s[qi][0];
#pragma unroll
            for (int kj = 1; kj < 8; kj++) tmax = fmaxf(tmax, s[qi][kj]);
#pragma unroll
            for (int off = 8; off > 0; off >>= 1)
                tmax = fmaxf(tmax, __shfl_xor_sync(0xffffffffu, tmax, off));

            float mn   = fmaxf(m[qi], tmax);
            float corr = __expf(m[qi] - mn);
            m[qi] = mn;

            float ps = 0.f;
#pragma unroll
            for (int kj = 0; kj < 8; kj++) {
                float p = __expf(s[qi][kj] - mn);
                s[qi][kj] = p;
                ps += p;
            }
#pragma unroll
            for (int off = 8; off > 0; off >>= 1)
                ps += __shfl_xor_sync(0xffffffffu, ps, off);

            l[qi] = l[qi] * corr + ps;
#pragma unroll
            for (int dj = 0; dj < 4; dj++) O[qi][dj] *= corr;
        }

        // ---- write P transposed to smem: Ps[k][q] ----
#pragma unroll
        for (int kj = 0; kj < 8; kj++) {
            float* dst = Ps + (tx * 8 + kj) * PS_STRIDE + ty * 8;
            *(float4*)dst       = make_float4(s[0][kj], s[1][kj], s[2][kj], s[3][kj]);
            *(float4*)(dst + 4) = make_float4(s[4][kj], s[5][kj], s[6][kj], s[7][kj]);
        }
        __syncthreads();

        // ---- O += P @ V : 8 q x 4 dims per thread (16 tx * 4 = 64 dims) ----
#pragma unroll 4
        for (int k = 0; k < 128; k++) {
            float4 p0 = *(const float4*)(Ps + k * PS_STRIDE + ty * 8);
            float4 p1 = *(const float4*)(Ps + k * PS_STRIDE + ty * 8 + 4);
            float4 v0 = *(const float4*)(Vs + k * 64 + tx * 4);
            float pr[8] = {p0.x, p0.y, p0.z, p0.w, p1.x, p1.y, p1.z, p1.w};
            float vr[4] = {v0.x, v0.y, v0.z, v0.w};
#pragma unroll
            for (int qi = 0; qi < 8; qi++)
#pragma unroll
                for (int dj = 0; dj < 4; dj++)
                    O[qi][dj] += pr[qi] * vr[dj];
        }
        __syncthreads();
    }

    // ---- epilogue: normalize and store (4 dims per thread, in-bounds) ----
#pragma unroll
    for (int qi = 0; qi < 8; qi++) {
        float inv = 1.0f / l[qi];
        int row = b * LQ + q0 + ty * 8 + qi;
        float4 o0 = make_float4(O[qi][0] * inv, O[qi][1] * inv,
                                O[qi][2] * inv, O[qi][3] * inv);
        *(float4*)(out + row * NF + tx * 4) = o0;
    }
}

// ---------------------------------------------------------------------------
extern "C" void kernel_launch(void* const* d_in, const int* in_sizes, int n_in,
                              void* d_out, int out_size)
{
    // Identify inputs by element count (tolerating byte counts), with a
    // positional fallback matching reference order: x, kv, Wq, Wk, Wv.
    const int NX = Bn * LQ * NF;   // 4194304
    const int NK = Bn * LK * NF;   //  524288
    const int NW = NF * NF;        //    4096

    const float* x  = nullptr;
    const float* kv = nullptr;
    const float* W[3] = {nullptr, nullptr, nullptr};
    int wn = 0;
    for (int i = 0; i < n_in; i++) {
        int s = in_sizes[i];
        if (s == NX || s == NX * 4)            x  = (const float*)d_in[i];
        else if (s == NK || s == NK * 4)       kv = (const float*)d_in[i];
        else if ((s == NW || s == NW * 4) && wn < 3) W[wn++] = (const float*)d_in[i];
    }
    if (!x || !kv || wn < 3) {   // fallback: reference order
        x  = (const float*)d_in[0];
        kv = (const float*)d_in[1];
        W[0] = (const float*)d_in[2];
        W[1] = (const float*)d_in[3];
        W[2] = (const float*)d_in[4];
    }
    const float* Wq = W[0];
    const float* Wk = W[1];
    const float* Wv = W[2];
    float* out = (float*)d_out;

    const int kvproj_smem = (4096 + 4096 + 64 * 65) * 4;                  // 49408
    const int attn_smem   = (64 * QS_STRIDE + 64 * 128 + 128 * 64
                             + 128 * PS_STRIDE) * 4;                      // 166912

    cudaFuncSetAttribute(kvproj_kernel,
                         cudaFuncAttributeMaxDynamicSharedMemorySize, kvproj_smem);
    cudaFuncSetAttribute(attn_kernel,
                         cudaFuncAttributeMaxDynamicSharedMemorySize, attn_smem);

    kvproj_kernel<<<Bn * (LK / 64), 256, kvproj_smem>>>(kv, Wk, Wv);
    attn_kernel<<<Bn * (LQ / 128), 256, attn_smem>>>(x, Wq, out);
}

// round 14
// speedup vs baseline: 2.0530x; 2.0530x over previous
#include <cuda_runtime.h>
#include <cuda_bf16.h>
#include <math.h>
#include <stdint.h>

#define Bn   8
#define LQ   8192
#define LK   1024
#define NF   64

// bf16 hi/lo split operands produced by prep kernel
__device__ __align__(16) __nv_bfloat16 g_Kh [Bn * LK * NF];  // [b][k][e]
__device__ __align__(16) __nv_bfloat16 g_Kl [Bn * LK * NF];
__device__ __align__(16) __nv_bfloat16 g_Vth[Bn * NF * LK];  // [b][e][k]
__device__ __align__(16) __nv_bfloat16 g_Vtl[Bn * NF * LK];

// ---------------------------------------------------------------------------
// helpers
// ---------------------------------------------------------------------------
__device__ __forceinline__ uint32_t smem_u32(const void* p) {
    uint32_t a;
    asm("{ .reg .u64 t; cvta.to.shared.u64 t, %1; cvt.u32.u64 %0, t; }"
        : "=r"(a) : "l"(p));
    return a;
}

__device__ __forceinline__ void ldsm4(uint32_t& r0, uint32_t& r1,
                                      uint32_t& r2, uint32_t& r3, uint32_t a) {
    asm volatile("ldmatrix.sync.aligned.m8n8.x4.shared.b16 {%0,%1,%2,%3}, [%4];"
                 : "=r"(r0), "=r"(r1), "=r"(r2), "=r"(r3) : "r"(a));
}

__device__ __forceinline__ void mma16816(float* c,
    uint32_t a0, uint32_t a1, uint32_t a2, uint32_t a3,
    uint32_t b0, uint32_t b1) {
    asm volatile("mma.sync.aligned.m16n8k16.row.col.f32.bf16.bf16.f32 "
                 "{%0,%1,%2,%3}, {%4,%5,%6,%7}, {%8,%9}, {%0,%1,%2,%3};"
                 : "+f"(c[0]), "+f"(c[1]), "+f"(c[2]), "+f"(c[3])
                 : "r"(a0), "r"(a1), "r"(a2), "r"(a3), "r"(b0), "r"(b1));
}

// pack two floats -> bf16x2 (lo in low half, hi in high half)
__device__ __forceinline__ uint32_t pack_bf16(float lo, float hi) {
    uint32_t r;
    asm("cvt.rn.bf16x2.f32 %0, %1, %2;" : "=r"(r) : "f"(hi), "f"(lo));
    return r;
}

// v ~= hi + lo, hi exactly representable in bf16 (RN)
__device__ __forceinline__ void split2(float v, float& hi, float& lo) {
    hi = __bfloat162float(__float2bfloat16(v));
    lo = v - hi;
}

__device__ __forceinline__ void split_us(float v, unsigned short& h,
                                         unsigned short& l) {
    __nv_bfloat16 bh = __float2bfloat16(v);
    float r = v - __bfloat162float(bh);
    __nv_bfloat16 bl = __float2bfloat16(r);
    h = __bfloat16_as_ushort(bh);
    l = __bfloat16_as_ushort(bl);
}

// ---------------------------------------------------------------------------
// Kernel 1: project kv -> Kh/Kl [b][k][e], Vth/Vtl [b][e][k] (bf16 split).
// grid = 128 blocks, 256 threads. smem 49408 B.
// ---------------------------------------------------------------------------
__global__ __launch_bounds__(256) void prep_kernel(
    const float* __restrict__ kv,
    const float* __restrict__ Wk,
    const float* __restrict__ Wv)
{
    int b  = blockIdx.x >> 4;
    int k0 = (blockIdx.x & 15) * 64;

    extern __shared__ float sm[];
    float* s_kv = sm;            // 64 x 64
    float* s_w  = sm + 4096;     // 64 x 64
    float* s_o  = sm + 8192;     // 64 x 65

    int tid = threadIdx.x;

    for (int i = tid; i < 4096; i += 256)
        s_kv[i] = kv[(b * LK + k0) * NF + i];
    for (int i = tid; i < 4096; i += 256)
        s_w[i] = Wk[i];
    __syncthreads();

    for (int i = tid; i < 4096; i += 256) {
        int k = i >> 6, e = i & 63;
        float acc = 0.f;
#pragma unroll
        for (int d = 0; d < 64; d++)
            acc += s_kv[k * 64 + d] * s_w[d * 64 + e];
        s_o[k * 65 + e] = acc;
    }
    __syncthreads();
    for (int i = tid; i < 4096; i += 256) {
        int k = i >> 6, e = i & 63;
        unsigned short h, l;
        split_us(s_o[k * 65 + e], h, l);
        int gi = (b * LK + k0 + k) * NF + e;
        g_Kh[gi] = __ushort_as_bfloat16(h);
        g_Kl[gi] = __ushort_as_bfloat16(l);
    }
    __syncthreads();

    for (int i = tid; i < 4096; i += 256) s_w[i] = Wv[i];
    __syncthreads();

    for (int i = tid; i < 4096; i += 256) {
        int k = i >> 6, e = i & 63;
        float acc = 0.f;
#pragma unroll
        for (int d = 0; d < 64; d++)
            acc += s_kv[k * 64 + d] * s_w[d * 64 + e];
        s_o[k * 65 + e] = acc;
    }
    __syncthreads();
    for (int i = tid; i < 4096; i += 256) {
        int d = i >> 6, k = i & 63;
        unsigned short h, l;
        split_us(s_o[k * 65 + d], h, l);
        int gi = (b * NF + d) * LK + k0 + k;
        g_Vth[gi] = __ushort_as_bfloat16(h);
        g_Vtl[gi] = __ushort_as_bfloat16(l);
    }
}

// ---------------------------------------------------------------------------
// Kernel 2: fused Q-proj + one-pass flash attention on mma.sync bf16 x3.
// grid = 512, block = 256 (8 warps). Warp w owns q rows [16w, 16w+16).
// smem layout (bytes):
//   QH 0      (128 rows x 72 bf16 = 18432)   QL 18432
//   KH 36864  (128 x 72)                      KL 55296
//   VH 73728  (64 rows x 136 bf16 = 17408)    VL 91136
//   prologue aliases Wq(16KB)+X(32KB) over KH..VL region
// ---------------------------------------------------------------------------
#define QH_OFF 0
#define QL_OFF 18432
#define KH_OFF 36864
#define KL_OFF 55296
#define VH_OFF 73728
#define VL_OFF 91136
#define SMEM_ATT 108544

__global__ __launch_bounds__(256, 1) void attn_kernel(
    const float* __restrict__ x,
    const float* __restrict__ Wq,
    float* __restrict__ out)
{
    extern __shared__ char smc[];
    const uint32_t sb = smem_u32(smc);
    int tid  = threadIdx.x;
    int w    = tid >> 5, lane = tid & 31;
    int b    = blockIdx.x >> 6;
    int q0   = (blockIdx.x & 63) * 128;

    // ---- prologue: Q = x @ Wq (fp32), split to bf16 hi/lo in smem ----
    {
        float* Wqs = (float*)(smc + KH_OFF);
        float* Xs  = (float*)(smc + KH_OFF + 16384);
        for (int i = tid; i < 4096; i += 256) Wqs[i] = Wq[i];
        for (int i = tid; i < 8192; i += 256) Xs[i] = x[(b * LQ + q0) * NF + i];
        __syncthreads();
        for (int i = tid; i < 8192; i += 256) {
            int q = i >> 6, e = i & 63;
            float acc = 0.f;
#pragma unroll
            for (int d = 0; d < 64; d++)
                acc += Xs[q * 64 + d] * Wqs[d * 64 + e];
            unsigned short h, l;
            split_us(acc, h, l);
            *(unsigned short*)(smc + QH_OFF + q * 144 + e * 2) = h;
            *(unsigned short*)(smc + QL_OFF + q * 144 + e * 2) = l;
        }
        __syncthreads();
    }

    // ---- load Q A-fragments (held in registers for whole kernel) ----
    uint32_t qh[4][4], ql[4][4];
    {
        int row = w * 16 + (lane & 15);
        int csel = (lane >> 4) * 8;
#pragma unroll
        for (int kk = 0; kk < 4; kk++) {
            uint32_t a = sb + QH_OFF + row * 144 + (kk * 16 + csel) * 2;
            ldsm4(qh[kk][0], qh[kk][1], qh[kk][2], qh[kk][3], a);
            a = sb + QL_OFF + row * 144 + (kk * 16 + csel) * 2;
            ldsm4(ql[kk][0], ql[kk][1], ql[kk][2], ql[kk][3], a);
        }
    }

    float m_lo = -3.0e38f, m_hi = -3.0e38f, l_lo = 0.f, l_hi = 0.f;
    float o[8][4];
#pragma unroll
    for (int i = 0; i < 8; i++) { o[i][0]=0; o[i][1]=0; o[i][2]=0; o[i][3]=0; }

    // per-lane ldmatrix B-frag address components
    const int brow = (lane & 7) + ((lane >> 4) << 3);   // key/dim row within 16
    const int bcol = ((lane >> 3) & 1) << 3;            // inner-dim col {0,8}

    for (int kt = 0; kt < 8; kt++) {
        __syncthreads();   // protect previous tile's smem from overwrite
        {
            const uint4* gkh = (const uint4*)g_Kh + ((size_t)(b * LK + kt * 128)) * 8;
            const uint4* gkl = (const uint4*)g_Kl + ((size_t)(b * LK + kt * 128)) * 8;
            for (int i = tid; i < 1024; i += 256) {
                int k = i >> 3, e8 = i & 7;
                *(uint4*)(smc + KH_OFF + k * 144 + e8 * 16) = gkh[i];
                *(uint4*)(smc + KL_OFF + k * 144 + e8 * 16) = gkl[i];
            }
            const uint4* gvh = (const uint4*)g_Vth + (size_t)b * (NF * LK / 8);
            const uint4* gvl = (const uint4*)g_Vtl + (size_t)b * (NF * LK / 8);
            for (int i = tid; i < 1024; i += 256) {
                int d = i >> 4, c = i & 15;
                *(uint4*)(smc + VH_OFF + d * 272 + c * 16) = gvh[d * 128 + kt * 16 + c];
                *(uint4*)(smc + VL_OFF + d * 272 + c * 16) = gvl[d * 128 + kt * 16 + c];
            }
        }
        __syncthreads();

        // ---- scores S[16 q][128 k]: c-frags sc[16 ntile][4] ----
        float sc[16][4];
#pragma unroll
        for (int i = 0; i < 16; i++) { sc[i][0]=0; sc[i][1]=0; sc[i][2]=0; sc[i][3]=0; }

#pragma unroll
        for (int np = 0; np < 8; np++) {
#pragma unroll
            for (int kk = 0; kk < 4; kk++) {
                uint32_t b0, b1, b2, b3;
                uint32_t a = sb + KH_OFF + (np * 16 + brow) * 144
                           + (kk * 16 + bcol) * 2;
                ldsm4(b0, b1, b2, b3, a);
                mma16816(sc[2*np],   qh[kk][0], qh[kk][1], qh[kk][2], qh[kk][3], b0, b1);
                mma16816(sc[2*np+1], qh[kk][0], qh[kk][1], qh[kk][2], qh[kk][3], b2, b3);
                mma16816(sc[2*np],   ql[kk][0], ql[kk][1], ql[kk][2], ql[kk][3], b0, b1);
                mma16816(sc[2*np+1], ql[kk][0], ql[kk][1], ql[kk][2], ql[kk][3], b2, b3);
                a = sb + KL_OFF + (np * 16 + brow) * 144 + (kk * 16 + bcol) * 2;
                ldsm4(b0, b1, b2, b3, a);
                mma16816(sc[2*np],   qh[kk][0], qh[kk][1], qh[kk][2], qh[kk][3], b0, b1);
                mma16816(sc[2*np+1], qh[kk][0], qh[kk][1], qh[kk][2], qh[kk][3], b2, b3);
            }
        }

        // ---- online softmax (rows: lo = lane/4, hi = lane/4+8) ----
        float tmax_lo = sc[0][0], tmax_hi = sc[0][2];
#pragma unroll
        for (int j = 0; j < 16; j++) {
            tmax_lo = fmaxf(tmax_lo, fmaxf(sc[j][0], sc[j][1]));
            tmax_hi = fmaxf(tmax_hi, fmaxf(sc[j][2], sc[j][3]));
        }
        tmax_lo = fmaxf(tmax_lo, __shfl_xor_sync(0xffffffffu, tmax_lo, 1));
        tmax_lo = fmaxf(tmax_lo, __shfl_xor_sync(0xffffffffu, tmax_lo, 2));
        tmax_hi = fmaxf(tmax_hi, __shfl_xor_sync(0xffffffffu, tmax_hi, 1));
        tmax_hi = fmaxf(tmax_hi, __shfl_xor_sync(0xffffffffu, tmax_hi, 2));

        float mn_lo = fmaxf(m_lo, tmax_lo), mn_hi = fmaxf(m_hi, tmax_hi);
        float cor_lo = __expf(m_lo - mn_lo), cor_hi = __expf(m_hi - mn_hi);
        m_lo = mn_lo; m_hi = mn_hi;

        float s_lo = 0.f, s_hi = 0.f;
#pragma unroll
        for (int j = 0; j < 16; j++) {
            sc[j][0] = __expf(sc[j][0] - mn_lo); s_lo += sc[j][0];
            sc[j][1] = __expf(sc[j][1] - mn_lo); s_lo += sc[j][1];
            sc[j][2] = __expf(sc[j][2] - mn_hi); s_hi += sc[j][2];
            sc[j][3] = __expf(sc[j][3] - mn_hi); s_hi += sc[j][3];
        }
        s_lo += __shfl_xor_sync(0xffffffffu, s_lo, 1);
        s_lo += __shfl_xor_sync(0xffffffffu, s_lo, 2);
        s_hi += __shfl_xor_sync(0xffffffffu, s_hi, 1);
        s_hi += __shfl_xor_sync(0xffffffffu, s_hi, 2);
        l_lo = l_lo * cor_lo + s_lo;
        l_hi = l_hi * cor_hi + s_hi;
#pragma unroll
        for (int i = 0; i < 8; i++) {
            o[i][0] *= cor_lo; o[i][1] *= cor_lo;
            o[i][2] *= cor_hi; o[i][3] *= cor_hi;
        }

        // ---- O += P @ V : C-frags tile directly into A-frags ----
#pragma unroll
        for (int kp = 0; kp < 8; kp++) {
            uint32_t ah[4], al[4];
            float h0, lo0, h1, lo1;
            split2(sc[2*kp][0], h0, lo0);  split2(sc[2*kp][1], h1, lo1);
            ah[0] = pack_bf16(h0, h1);     al[0] = pack_bf16(lo0, lo1);
            split2(sc[2*kp][2], h0, lo0);  split2(sc[2*kp][3], h1, lo1);
            ah[1] = pack_bf16(h0, h1);     al[1] = pack_bf16(lo0, lo1);
            split2(sc[2*kp+1][0], h0, lo0); split2(sc[2*kp+1][1], h1, lo1);
            ah[2] = pack_bf16(h0, h1);     al[2] = pack_bf16(lo0, lo1);
            split2(sc[2*kp+1][2], h0, lo0); split2(sc[2*kp+1][3], h1, lo1);
            ah[3] = pack_bf16(h0, h1);     al[3] = pack_bf16(lo0, lo1);

#pragma unroll
            for (int dp = 0; dp < 4; dp++) {
                uint32_t b0, b1, b2, b3;
                uint32_t a = sb + VH_OFF + (dp * 16 + brow) * 272
                           + (kp * 16 + bcol) * 2;
                ldsm4(b0, b1, b2, b3, a);
                mma16816(o[2*dp],   ah[0], ah[1], ah[2], ah[3], b0, b1);
                mma16816(o[2*dp+1], ah[0], ah[1], ah[2], ah[3], b2, b3);
                mma16816(o[2*dp],   al[0], al[1], al[2], al[3], b0, b1);
                mma16816(o[2*dp+1], al[0], al[1], al[2], al[3], b2, b3);
                a = sb + VL_OFF + (dp * 16 + brow) * 272 + (kp * 16 + bcol) * 2;
                ldsm4(b0, b1, b2, b3, a);
                mma16816(o[2*dp],   ah[0], ah[1], ah[2], ah[3], b0, b1);
                mma16816(o[2*dp+1], ah[0], ah[1], ah[2], ah[3], b2, b3);
            }
        }
    }

    // ---- epilogue ----
    float inv_lo = 1.0f / l_lo, inv_hi = 1.0f / l_hi;
    size_t q_lo = (size_t)(b * LQ + q0 + w * 16 + (lane >> 2));
    int col = (lane & 3) << 1;
#pragma unroll
    for (int dn = 0; dn < 8; dn++) {
        *(float2*)(out + q_lo * NF + dn * 8 + col) =
            make_float2(o[dn][0] * inv_lo, o[dn][1] * inv_lo);
        *(float2*)(out + (q_lo + 8) * NF + dn * 8 + col) =
            make_float2(o[dn][2] * inv_hi, o[dn][3] * inv_hi);
    }
}

// ---------------------------------------------------------------------------
extern "C" void kernel_launch(void* const* d_in, const int* in_sizes, int n_in,
                              void* d_out, int out_size)
{
    const int NX = Bn * LQ * NF, NK = Bn * LK * NF, NW = NF * NF;
    const float* x  = nullptr;
    const float* kv = nullptr;
    const float* W[3] = {nullptr, nullptr, nullptr};
    int wn = 0;
    for (int i = 0; i < n_in; i++) {
        int s = in_sizes[i];
        if (s == NX)       x  = (const float*)d_in[i];
        else if (s == NK)  kv = (const float*)d_in[i];
        else if (s == NW && wn < 3) W[wn++] = (const float*)d_in[i];
    }
    if (!x || !kv || wn < 3) {
        x  = (const float*)d_in[0];
        kv = (const float*)d_in[1];
        W[0] = (const float*)d_in[2];
        W[1] = (const float*)d_in[3];
        W[2] = (const float*)d_in[4];
    }
    float* out = (float*)d_out;

    const int prep_smem = (4096 + 4096 + 64 * 65) * 4;  // 49408
    cudaFuncSetAttribute(prep_kernel,
                         cudaFuncAttributeMaxDynamicSharedMemorySize, prep_smem);
    cudaFuncSetAttribute(attn_kernel,
                         cudaFuncAttributeMaxDynamicSharedMemorySize, SMEM_ATT);

    prep_kernel<<<Bn * (LK / 64), 256, prep_smem>>>(kv, W[1], W[2]);
    attn_kernel<<<Bn * (LQ / 128), 256, SMEM_ATT>>>(x, W[0], out);
}

// round 15
// speedup vs baseline: 2.4424x; 1.1897x over previous
#include <cuda_runtime.h>
#include <cuda_bf16.h>
#include <math.h>
#include <stdint.h>

#define Bn   8
#define LQ   8192
#define LK   1024
#define NF   64

// bf16 hi/lo split operands produced by prep kernel
__device__ __align__(16) __nv_bfloat16 g_Kh [Bn * LK * NF];  // [b][k][e]
__device__ __align__(16) __nv_bfloat16 g_Kl [Bn * LK * NF];
__device__ __align__(16) __nv_bfloat16 g_Vth[Bn * NF * LK];  // [b][e][k]
__device__ __align__(16) __nv_bfloat16 g_Vtl[Bn * NF * LK];

// ---------------------------------------------------------------------------
// helpers
// ---------------------------------------------------------------------------
__device__ __forceinline__ uint32_t smem_u32(const void* p) {
    uint32_t a;
    asm("{ .reg .u64 t; cvta.to.shared.u64 t, %1; cvt.u32.u64 %0, t; }"
        : "=r"(a) : "l"(p));
    return a;
}

__device__ __forceinline__ void ldsm4(uint32_t& r0, uint32_t& r1,
                                      uint32_t& r2, uint32_t& r3, uint32_t a) {
    asm volatile("ldmatrix.sync.aligned.m8n8.x4.shared.b16 {%0,%1,%2,%3}, [%4];"
                 : "=r"(r0), "=r"(r1), "=r"(r2), "=r"(r3) : "r"(a));
}

__device__ __forceinline__ void mma16816(float* c,
    uint32_t a0, uint32_t a1, uint32_t a2, uint32_t a3,
    uint32_t b0, uint32_t b1) {
    asm volatile("mma.sync.aligned.m16n8k16.row.col.f32.bf16.bf16.f32 "
                 "{%0,%1,%2,%3}, {%4,%5,%6,%7}, {%8,%9}, {%0,%1,%2,%3};"
                 : "+f"(c[0]), "+f"(c[1]), "+f"(c[2]), "+f"(c[3])
                 : "r"(a0), "r"(a1), "r"(a2), "r"(a3), "r"(b0), "r"(b1));
}

// pack two floats -> bf16x2 (lo arg in low half, hi arg in high half)
__device__ __forceinline__ uint32_t pack_bf16(float lo, float hi) {
    uint32_t r;
    asm("cvt.rn.bf16x2.f32 %0, %1, %2;" : "=r"(r) : "f"(hi), "f"(lo));
    return r;
}

// v ~= hi + lo, hi exactly representable in bf16 (RN)
__device__ __forceinline__ void split2(float v, float& hi, float& lo) {
    hi = __bfloat162float(__float2bfloat16(v));
    lo = v - hi;
}

__device__ __forceinline__ void split_us(float v, unsigned short& h,
                                         unsigned short& l) {
    __nv_bfloat16 bh = __float2bfloat16(v);
    float r = v - __bfloat162float(bh);
    __nv_bfloat16 bl = __float2bfloat16(r);
    h = __bfloat16_as_ushort(bh);
    l = __bfloat16_as_ushort(bl);
}

// ---------------------------------------------------------------------------
// Kernel 1: project kv -> Kh/Kl [b][k][e], Vth/Vtl [b][e][k] (bf16 split).
// grid = 128 blocks, 256 threads. smem 49408 B.
// ---------------------------------------------------------------------------
__global__ __launch_bounds__(256) void prep_kernel(
    const float* __restrict__ kv,
    const float* __restrict__ Wk,
    const float* __restrict__ Wv)
{
    int b  = blockIdx.x >> 4;
    int k0 = (blockIdx.x & 15) * 64;

    extern __shared__ float sm[];
    float* s_kv = sm;            // 64 x 64
    float* s_w  = sm + 4096;     // 64 x 64
    float* s_o  = sm + 8192;     // 64 x 65

    int tid = threadIdx.x;

    for (int i = tid; i < 4096; i += 256)
        s_kv[i] = kv[(b * LK + k0) * NF + i];
    for (int i = tid; i < 4096; i += 256)
        s_w[i] = Wk[i];
    __syncthreads();

    for (int i = tid; i < 4096; i += 256) {
        int k = i >> 6, e = i & 63;
        float acc = 0.f;
#pragma unroll
        for (int d = 0; d < 64; d++)
            acc += s_kv[k * 64 + d] * s_w[d * 64 + e];
        s_o[k * 65 + e] = acc;
    }
    __syncthreads();
    for (int i = tid; i < 4096; i += 256) {
        int k = i >> 6, e = i & 63;
        unsigned short h, l;
        split_us(s_o[k * 65 + e], h, l);
        int gi = (b * LK + k0 + k) * NF + e;
        g_Kh[gi] = __ushort_as_bfloat16(h);
        g_Kl[gi] = __ushort_as_bfloat16(l);
    }
    __syncthreads();

    for (int i = tid; i < 4096; i += 256) s_w[i] = Wv[i];
    __syncthreads();

    for (int i = tid; i < 4096; i += 256) {
        int k = i >> 6, e = i & 63;
        float acc = 0.f;
#pragma unroll
        for (int d = 0; d < 64; d++)
            acc += s_kv[k * 64 + d] * s_w[d * 64 + e];
        s_o[k * 65 + e] = acc;
    }
    __syncthreads();
    for (int i = tid; i < 4096; i += 256) {
        int d = i >> 6, k = i & 63;
        unsigned short h, l;
        split_us(s_o[k * 65 + d], h, l);
        int gi = (b * NF + d) * LK + k0 + k;
        g_Vth[gi] = __ushort_as_bfloat16(h);
        g_Vtl[gi] = __ushort_as_bfloat16(l);
    }
}

// ---------------------------------------------------------------------------
// Kernel 2: fused Q-proj + one-pass flash attention on mma.sync bf16 x3.
// grid = Bn * (LQ/64) = 1024, block = 128 (4 warps), 2 CTAs/SM.
// Warp w owns q rows [16w, 16w+16) of the 64-row tile.
// smem layout (bytes), total 90112:
//   QH 0      (64 x 72 bf16 = 9216)     QL 9216
//   KH 18432  (128 x 72 = 18432)        KL 36864
//   VH 55296  (64 x 136 = 17408)        VL 72704
//   prologue aliases Wq(16KB)+X(16KB) over KH..KL region
// ---------------------------------------------------------------------------
#define QH_OFF 0
#define QL_OFF 9216
#define KH_OFF 18432
#define KL_OFF 36864
#define VH_OFF 55296
#define VL_OFF 72704
#define SMEM_ATT 90112

__global__ __launch_bounds__(128, 2) void attn_kernel(
    const float* __restrict__ x,
    const float* __restrict__ Wq,
    float* __restrict__ out)
{
    extern __shared__ char smc[];
    const uint32_t sb = smem_u32(smc);
    int tid  = threadIdx.x;
    int w    = tid >> 5, lane = tid & 31;
    int b    = blockIdx.x >> 7;
    int q0   = (blockIdx.x & 127) * 64;

    // ---- prologue: Q = x @ Wq (fp32), split to bf16 hi/lo in smem ----
    {
        float* Wqs = (float*)(smc + KH_OFF);
        float* Xs  = (float*)(smc + KH_OFF + 16384);
        for (int i = tid; i < 4096; i += 128) Wqs[i] = Wq[i];
        for (int i = tid; i < 4096; i += 128) Xs[i] = x[(b * LQ + q0) * NF + i];
        __syncthreads();
        for (int i = tid; i < 4096; i += 128) {
            int q = i >> 6, e = i & 63;
            float acc = 0.f;
#pragma unroll
            for (int d = 0; d < 64; d++)
                acc += Xs[q * 64 + d] * Wqs[d * 64 + e];
            unsigned short h, l;
            split_us(acc, h, l);
            *(unsigned short*)(smc + QH_OFF + q * 144 + e * 2) = h;
            *(unsigned short*)(smc + QL_OFF + q * 144 + e * 2) = l;
        }
        __syncthreads();
    }

    // ---- load Q A-fragments (held in registers for whole kernel) ----
    uint32_t qh[4][4], ql[4][4];
    {
        int row = w * 16 + (lane & 15);
        int csel = (lane >> 4) * 8;
#pragma unroll
        for (int kk = 0; kk < 4; kk++) {
            uint32_t a = sb + QH_OFF + row * 144 + (kk * 16 + csel) * 2;
            ldsm4(qh[kk][0], qh[kk][1], qh[kk][2], qh[kk][3], a);
            a = sb + QL_OFF + row * 144 + (kk * 16 + csel) * 2;
            ldsm4(ql[kk][0], ql[kk][1], ql[kk][2], ql[kk][3], a);
        }
    }

    float m_lo = -3.0e38f, m_hi = -3.0e38f, l_lo = 0.f, l_hi = 0.f;
    float o[8][4];
#pragma unroll
    for (int i = 0; i < 8; i++) { o[i][0]=0; o[i][1]=0; o[i][2]=0; o[i][3]=0; }

    // per-lane ldmatrix B-frag address components
    const int brow = (lane & 7) + ((lane >> 4) << 3);   // key/dim row within 16
    const int bcol = ((lane >> 3) & 1) << 3;            // inner-dim col {0,8}

    for (int kt = 0; kt < 8; kt++) {
        __syncthreads();   // protect previous tile's smem from overwrite
        {
            const uint4* gkh = (const uint4*)g_Kh + ((size_t)(b * LK + kt * 128)) * 8;
            const uint4* gkl = (const uint4*)g_Kl + ((size_t)(b * LK + kt * 128)) * 8;
            for (int i = tid; i < 1024; i += 128) {
                int k = i >> 3, e8 = i & 7;
                *(uint4*)(smc + KH_OFF + k * 144 + e8 * 16) = gkh[i];
                *(uint4*)(smc + KL_OFF + k * 144 + e8 * 16) = gkl[i];
            }
            const uint4* gvh = (const uint4*)g_Vth + (size_t)b * (NF * LK / 8);
            const uint4* gvl = (const uint4*)g_Vtl + (size_t)b * (NF * LK / 8);
            for (int i = tid; i < 1024; i += 128) {
                int d = i >> 4, c = i & 15;
                *(uint4*)(smc + VH_OFF + d * 272 + c * 16) = gvh[d * 128 + kt * 16 + c];
                *(uint4*)(smc + VL_OFF + d * 272 + c * 16) = gvl[d * 128 + kt * 16 + c];
            }
        }
        __syncthreads();

        // ---- scores S[16 q][128 k]: c-frags sc[16 ntile][4] ----
        float sc[16][4];
#pragma unroll
        for (int i = 0; i < 16; i++) { sc[i][0]=0; sc[i][1]=0; sc[i][2]=0; sc[i][3]=0; }

#pragma unroll
        for (int np = 0; np < 8; np++) {
#pragma unroll
            for (int kk = 0; kk < 4; kk++) {
                uint32_t b0, b1, b2, b3;
                uint32_t a = sb + KH_OFF + (np * 16 + brow) * 144
                           + (kk * 16 + bcol) * 2;
                ldsm4(b0, b1, b2, b3, a);
                mma16816(sc[2*np],   qh[kk][0], qh[kk][1], qh[kk][2], qh[kk][3], b0, b1);
                mma16816(sc[2*np+1], qh[kk][0], qh[kk][1], qh[kk][2], qh[kk][3], b2, b3);
                mma16816(sc[2*np],   ql[kk][0], ql[kk][1], ql[kk][2], ql[kk][3], b0, b1);
                mma16816(sc[2*np+1], ql[kk][0], ql[kk][1], ql[kk][2], ql[kk][3], b2, b3);
                a = sb + KL_OFF + (np * 16 + brow) * 144 + (kk * 16 + bcol) * 2;
                ldsm4(b0, b1, b2, b3, a);
                mma16816(sc[2*np],   qh[kk][0], qh[kk][1], qh[kk][2], qh[kk][3], b0, b1);
                mma16816(sc[2*np+1], qh[kk][0], qh[kk][1], qh[kk][2], qh[kk][3], b2, b3);
            }
        }

        // ---- online softmax (rows: lo = lane/4, hi = lane/4+8) ----
        float tmax_lo = sc[0][0], tmax_hi = sc[0][2];
#pragma unroll
        for (int j = 0; j < 16; j++) {
            tmax_lo = fmaxf(tmax_lo, fmaxf(sc[j][0], sc[j][1]));
            tmax_hi = fmaxf(tmax_hi, fmaxf(sc[j][2], sc[j][3]));
        }
        tmax_lo = fmaxf(tmax_lo, __shfl_xor_sync(0xffffffffu, tmax_lo, 1));
        tmax_lo = fmaxf(tmax_lo, __shfl_xor_sync(0xffffffffu, tmax_lo, 2));
        tmax_hi = fmaxf(tmax_hi, __shfl_xor_sync(0xffffffffu, tmax_hi, 1));
        tmax_hi = fmaxf(tmax_hi, __shfl_xor_sync(0xffffffffu, tmax_hi, 2));

        float mn_lo = fmaxf(m_lo, tmax_lo), mn_hi = fmaxf(m_hi, tmax_hi);
        float cor_lo = __expf(m_lo - mn_lo), cor_hi = __expf(m_hi - mn_hi);
        m_lo = mn_lo; m_hi = mn_hi;

        float s_lo = 0.f, s_hi = 0.f;
#pragma unroll
        for (int j = 0; j < 16; j++) {
            sc[j][0] = __expf(sc[j][0] - mn_lo); s_lo += sc[j][0];
            sc[j][1] = __expf(sc[j][1] - mn_lo); s_lo += sc[j][1];
            sc[j][2] = __expf(sc[j][2] - mn_hi); s_hi += sc[j][2];
            sc[j][3] = __expf(sc[j][3] - mn_hi); s_hi += sc[j][3];
        }
        s_lo += __shfl_xor_sync(0xffffffffu, s_lo, 1);
        s_lo += __shfl_xor_sync(0xffffffffu, s_lo, 2);
        s_hi += __shfl_xor_sync(0xffffffffu, s_hi, 1);
        s_hi += __shfl_xor_sync(0xffffffffu, s_hi, 2);
        l_lo = l_lo * cor_lo + s_lo;
        l_hi = l_hi * cor_hi + s_hi;
#pragma unroll
        for (int i = 0; i < 8; i++) {
            o[i][0] *= cor_lo; o[i][1] *= cor_lo;
            o[i][2] *= cor_hi; o[i][3] *= cor_hi;
        }

        // ---- O += P @ V : C-frags tile directly into A-frags ----
#pragma unroll
        for (int kp = 0; kp < 8; kp++) {
            uint32_t ah[4], al[4];
            float h0, lo0, h1, lo1;
            split2(sc[2*kp][0], h0, lo0);  split2(sc[2*kp][1], h1, lo1);
            ah[0] = pack_bf16(h0, h1);     al[0] = pack_bf16(lo0, lo1);
            split2(sc[2*kp][2], h0, lo0);  split2(sc[2*kp][3], h1, lo1);
            ah[1] = pack_bf16(h0, h1);     al[1] = pack_bf16(lo0, lo1);
            split2(sc[2*kp+1][0], h0, lo0); split2(sc[2*kp+1][1], h1, lo1);
            ah[2] = pack_bf16(h0, h1);     al[2] = pack_bf16(lo0, lo1);
            split2(sc[2*kp+1][2], h0, lo0); split2(sc[2*kp+1][3], h1, lo1);
            ah[3] = pack_bf16(h0, h1);     al[3] = pack_bf16(lo0, lo1);

#pragma unroll
            for (int dp = 0; dp < 4; dp++) {
                uint32_t b0, b1, b2, b3;
                uint32_t a = sb + VH_OFF + (dp * 16 + brow) * 272
                           + (kp * 16 + bcol) * 2;
                ldsm4(b0, b1, b2, b3, a);
                mma16816(o[2*dp],   ah[0], ah[1], ah[2], ah[3], b0, b1);
                mma16816(o[2*dp+1], ah[0], ah[1], ah[2], ah[3], b2, b3);
                mma16816(o[2*dp],   al[0], al[1], al[2], al[3], b0, b1);
                mma16816(o[2*dp+1], al[0], al[1], al[2], al[3], b2, b3);
                a = sb + VL_OFF + (dp * 16 + brow) * 272 + (kp * 16 + bcol) * 2;
                ldsm4(b0, b1, b2, b3, a);
                mma16816(o[2*dp],   ah[0], ah[1], ah[2], ah[3], b0, b1);
                mma16816(o[2*dp+1], ah[0], ah[1], ah[2], ah[3], b2, b3);
            }
        }
    }

    // ---- epilogue ----
    float inv_lo = 1.0f / l_lo, inv_hi = 1.0f / l_hi;
    size_t q_lo = (size_t)(b * LQ + q0 + w * 16 + (lane >> 2));
    int col = (lane & 3) << 1;
#pragma unroll
    for (int dn = 0; dn < 8; dn++) {
        *(float2*)(out + q_lo * NF + dn * 8 + col) =
            make_float2(o[dn][0] * inv_lo, o[dn][1] * inv_lo);
        *(float2*)(out + (q_lo + 8) * NF + dn * 8 + col) =
            make_float2(o[dn][2] * inv_hi, o[dn][3] * inv_hi);
    }
}

// ---------------------------------------------------------------------------
extern "C" void kernel_launch(void* const* d_in, const int* in_sizes, int n_in,
                              void* d_out, int out_size)
{
    const int NX = Bn * LQ * NF, NK = Bn * LK * NF, NW = NF * NF;
    const float* x  = nullptr;
    const float* kv = nullptr;
    const float* W[3] = {nullptr, nullptr, nullptr};
    int wn = 0;
    for (int i = 0; i < n_in; i++) {
        int s = in_sizes[i];
        if (s == NX)       x  = (const float*)d_in[i];
        else if (s == NK)  kv = (const float*)d_in[i];
        else if (s == NW && wn < 3) W[wn++] = (const float*)d_in[i];
    }
    if (!x || !kv || wn < 3) {
        x  = (const float*)d_in[0];
        kv = (const float*)d_in[1];
        W[0] = (const float*)d_in[2];
        W[1] = (const float*)d_in[3];
        W[2] = (const float*)d_in[4];
    }
    float* out = (float*)d_out;

    const int prep_smem = (4096 + 4096 + 64 * 65) * 4;  // 49408
    cudaFuncSetAttribute(prep_kernel,
                         cudaFuncAttributeMaxDynamicSharedMemorySize, prep_smem);
    cudaFuncSetAttribute(attn_kernel,
                         cudaFuncAttributeMaxDynamicSharedMemorySize, SMEM_ATT);

    prep_kernel<<<Bn * (LK / 64), 256, prep_smem>>>(kv, W[1], W[2]);
    attn_kernel<<<Bn * (LQ / 64), 128, SMEM_ATT>>>(x, W[0], out);
}